// round 5
// baseline (speedup 1.0000x reference)
#include <cuda_runtime.h>
#include <cstdint>
#include <math.h>

// ---------------- problem constants ----------------
#define HW     16384      // 128*128
#define WIMG   128
#define C_IN   192
#define C3     576        // 3*C_IN
#define NB     8
#define HEADS  8
#define HD     24

// ---------------- scratch ----------------
__device__ float g_y  [16][C3 * HW];
__device__ float g_qkv[16][C3 * HW];
__device__ float g_S  [2][NB][HEADS][HD * HD];
__device__ float g_css[16][C3];                 // per-(z,ch) sum of squares of dw output
__device__ float g_M  [2][NB][C_IN * C_IN];

// ---------------- K0: zero accumulators ----------------
__global__ void k0_zero() {
    int idx = blockIdx.x * 256 + threadIdx.x;
    const int nS = 2 * NB * HEADS * HD * HD;     // 73728
    const int nC = 16 * C3;                      // 9216
    if (idx < nS) (&g_S[0][0][0][0])[idx] = 0.f;
    if (idx < nC) (&g_css[0][0])[idx] = 0.f;
}

// ---------------- tf32 helpers ----------------
__device__ __forceinline__ uint32_t f2tf32(float x) {
    uint32_t r;
    asm("cvt.rna.tf32.f32 %0, %1;" : "=r"(r) : "f"(x));
    return r;
}
__device__ __forceinline__ void mma_16x8x8(float* c, const uint32_t* a, const uint32_t* b) {
    asm volatile(
        "mma.sync.aligned.m16n8k8.row.col.f32.tf32.tf32.f32 "
        "{%0,%1,%2,%3}, {%4,%5,%6,%7}, {%8,%9}, {%0,%1,%2,%3};"
        : "+f"(c[0]), "+f"(c[1]), "+f"(c[2]), "+f"(c[3])
        : "r"(a[0]), "r"(a[1]), "r"(a[2]), "r"(a[3]), "r"(b[0]), "r"(b[1]));
}

// ---------------- mma tf32 GEMM: C[m0:m0+128, n0:n0+128] = A(.,192)@B(192,HW) ----------------
// 128 threads (4 warps), warp grid 2(M)x2(N), warp tile 64x64 = 4x8 m16n8k8.
__device__ __forceinline__ void gemm_mma_128x128(
    const float* __restrict__ A, const float* __restrict__ B, float* __restrict__ C,
    int m0, int n0)
{
    __shared__ uint32_t As[2][128][20];   // [m][k] stride 20: conflict-free
    __shared__ uint32_t Bs[2][16][136];   // [k][n] stride 136: conflict-free

    const int tid  = threadIdx.x;
    const int wid  = tid >> 5;
    const int lane = tid & 31;
    const int warp_m = wid & 1;           // 0..1 -> 64 rows
    const int warp_n = wid >> 1;          // 0..1 -> 64 cols
    const int lr = lane >> 2;
    const int lc = lane & 3;

    const int ar  = tid >> 2;             // 0..31 (+32,+64,+96)
    const int akq = (tid & 3) * 4;
    const int bkr = tid >> 5;             // 0..3 (+4,+8,+12)
    const int bnq = (tid & 31) * 4;

    const float* Ap = A + (size_t)(m0 + ar) * 192 + akq;
    const float* Bp = B + (size_t)bkr * HW + n0 + bnq;

    float4 ag[4], bg[4];
#pragma unroll
    for (int i = 0; i < 4; i++) {
        ag[i] = *(const float4*)(Ap + (size_t)i * 32 * 192);
        bg[i] = *(const float4*)(Bp + (size_t)i * 4 * HW);
    }
#pragma unroll
    for (int i = 0; i < 4; i++) {
        uint32_t* d = &As[0][ar + i * 32][akq];
        d[0] = f2tf32(ag[i].x); d[1] = f2tf32(ag[i].y); d[2] = f2tf32(ag[i].z); d[3] = f2tf32(ag[i].w);
        uint32_t* e = &Bs[0][bkr + i * 4][bnq];
        e[0] = f2tf32(bg[i].x); e[1] = f2tf32(bg[i].y); e[2] = f2tf32(bg[i].z); e[3] = f2tf32(bg[i].w);
    }
    __syncthreads();

    float acc[4][8][4];
#pragma unroll
    for (int i = 0; i < 4; i++)
#pragma unroll
        for (int j = 0; j < 8; j++)
#pragma unroll
            for (int q = 0; q < 4; q++) acc[i][j][q] = 0.f;

    int buf = 0;
    for (int ch = 0; ch < 12; ch++) {
        if (ch < 11) {
            const float* Apn = Ap + (ch + 1) * 16;
            const float* Bpn = Bp + (size_t)(ch + 1) * 16 * HW;
#pragma unroll
            for (int i = 0; i < 4; i++) {
                ag[i] = *(const float4*)(Apn + (size_t)i * 32 * 192);
                bg[i] = *(const float4*)(Bpn + (size_t)i * 4 * HW);
            }
        }
#pragma unroll
        for (int kst = 0; kst < 2; kst++) {
            const int k0 = kst * 8;
            uint32_t afr[4][4];
#pragma unroll
            for (int mt = 0; mt < 4; mt++) {
                int rb = warp_m * 64 + mt * 16 + lr;
                afr[mt][0] = As[buf][rb][k0 + lc];
                afr[mt][1] = As[buf][rb + 8][k0 + lc];
                afr[mt][2] = As[buf][rb][k0 + 4 + lc];
                afr[mt][3] = As[buf][rb + 8][k0 + 4 + lc];
            }
#pragma unroll
            for (int nt = 0; nt < 8; nt++) {
                uint32_t bfr[2];
                int nn = warp_n * 64 + nt * 8 + lr;
                bfr[0] = Bs[buf][k0 + lc][nn];
                bfr[1] = Bs[buf][k0 + 4 + lc][nn];
#pragma unroll
                for (int mt = 0; mt < 4; mt++)
                    mma_16x8x8(acc[mt][nt], afr[mt], bfr);
            }
        }
        if (ch < 11) {
            int nb = buf ^ 1;
#pragma unroll
            for (int i = 0; i < 4; i++) {
                uint32_t* d = &As[nb][ar + i * 32][akq];
                d[0] = f2tf32(ag[i].x); d[1] = f2tf32(ag[i].y); d[2] = f2tf32(ag[i].z); d[3] = f2tf32(ag[i].w);
                uint32_t* e = &Bs[nb][bkr + i * 4][bnq];
                e[0] = f2tf32(bg[i].x); e[1] = f2tf32(bg[i].y); e[2] = f2tf32(bg[i].z); e[3] = f2tf32(bg[i].w);
            }
            __syncthreads();
            buf = nb;
        }
    }

#pragma unroll
    for (int mt = 0; mt < 4; mt++) {
        int row = m0 + warp_m * 64 + mt * 16 + lr;
#pragma unroll
        for (int nt = 0; nt < 8; nt++) {
            int col = n0 + warp_n * 64 + nt * 8 + lc * 2;
            *(float2*)(C + (size_t)row * HW + col)       = make_float2(acc[mt][nt][0], acc[mt][nt][1]);
            *(float2*)(C + (size_t)(row + 8) * HW + col) = make_float2(acc[mt][nt][2], acc[mt][nt][3]);
        }
    }
}

// ---------------- K1: 1x1 qkv conv ----------------
__global__ void __launch_bounds__(128)
k1_qkv(const float* __restrict__ rgb, const float* __restrict__ ir,
       const float* __restrict__ wqkv)
{
    int z = blockIdx.z, s = z >> 3, b = z & 7;
    int m0 = blockIdx.y * 128;
    if (m0 > C3 - 128) m0 = C3 - 128;     // overlap: identical double-writes
    const float* x = (s ? ir : rgb) + (size_t)b * C_IN * HW;
    gemm_mma_128x128(wqkv, x, g_y[z], m0, blockIdx.x * 128);
}

// ---------------- K5: out = M @ V ----------------
__global__ void __launch_bounds__(128)
k5_out(float* __restrict__ out)
{
    int z = blockIdx.z;
    const float* A = g_M[z >> 3][z & 7];
    const float* V = g_qkv[z] + (size_t)(2 * C_IN) * HW;
    float* C = out + (size_t)z * C_IN * HW;
    int m0 = blockIdx.y * 64;             // 0 or 64 (overlap)
    gemm_mma_128x128(A, V, C, m0, blockIdx.x * 128);
}

// ---------------- K2: depthwise 3x3 SAME + per-channel sumsq ----------------
__global__ void k2_dw(const float* __restrict__ wdw)
{
    int z  = blockIdx.z;
    int ch = blockIdx.y;
    int n  = blockIdx.x * 1024 + threadIdx.x * 4;
    const float* yin = g_y[z]  + (size_t)ch * HW;
    float*       out = g_qkv[z] + (size_t)ch * HW;

    const float* w = wdw + ch * 9;
    float wr[3][3];
#pragma unroll
    for (int i = 0; i < 9; i++) wr[i / 3][i % 3] = w[i];

    int yy = n >> 7, xx = n & 127;
    bool xm = (xx > 0), xp = (xx < 124);
    float o0 = 0.f, o1 = 0.f, o2 = 0.f, o3 = 0.f;
#pragma unroll
    for (int r = 0; r < 3; r++) {
        int ry = yy + r - 1;
        if (ry < 0 || ry >= WIMG) continue;
        const float* row = yin + (size_t)ry * WIMG;
        float4 cv = *(const float4*)&row[xx];
        float lft = xm ? row[xx - 1] : 0.f;
        float rgt = xp ? row[xx + 4] : 0.f;
        float w0 = wr[r][0], w1 = wr[r][1], w2 = wr[r][2];
        o0 += w0 * lft  + w1 * cv.x + w2 * cv.y;
        o1 += w0 * cv.x + w1 * cv.y + w2 * cv.z;
        o2 += w0 * cv.y + w1 * cv.z + w2 * cv.w;
        o3 += w0 * cv.z + w1 * cv.w + w2 * rgt;
    }
    *(float4*)&out[n] = make_float4(o0, o1, o2, o3);

    // per-channel sum of squares (for F.normalize denominators)
    float ss = o0 * o0 + o1 * o1 + o2 * o2 + o3 * o3;
#pragma unroll
    for (int off = 16; off; off >>= 1) ss += __shfl_xor_sync(0xFFFFFFFFu, ss, off);
    if ((threadIdx.x & 31) == 0) atomicAdd(&g_css[z][ch], ss);
}

// ---------------- K3: channel Gram (2x2 per thread, rows split by +12) ----------------
// t=0: q = iq (s=1), k = rk (s=0);  t=1: q = rq (s=0), k = ik (s=1)
__global__ void k3_gram()
{
    int t  = blockIdx.z;
    int bh = blockIdx.y;
    int b = bh >> 3, h = bh & 7;
    int n0 = blockIdx.x * 1024;

    int qs = (t == 0) ? 1 : 0;
    int kstream = 1 - qs;
    const float* qbase = g_qkv[qs * 8 + b]      + (size_t)(h * HD) * HW + n0;
    const float* kbase = g_qkv[kstream * 8 + b] + (size_t)(C_IN + h * HD) * HW + n0;

    __shared__ float qsm[HD][132];
    __shared__ float ksm[HD][132];

    int tid = threadIdx.x;                // 576 = 4 k-groups x 144
    int g = tid / 144;                    // 0..3 -> j quarter
    int r = tid - g * 144;
    int c = r / 12;                       // 0..11 (rows c, c+12)
    int d = r - c * 12;                   // 0..11 (rows d, d+12)
    const int jb = g * 32;

    float a00 = 0.f, a01 = 0.f, a10 = 0.f, a11 = 0.f;

    for (int ch0 = 0; ch0 < 1024; ch0 += 128) {
        __syncthreads();
        for (int i = tid; i < 2 * HD * 32; i += 576) {   // 1536 float4s
            int arr = (i >= 768);
            int li  = arr ? (i - 768) : i;
            int row = li >> 5;
            int c4  = (li & 31) * 4;
            const float* src = arr ? kbase : qbase;
            float4 v = *(const float4*)&src[(size_t)row * HW + ch0 + c4];
            if (arr) *(float4*)&ksm[row][c4] = v;
            else     *(float4*)&qsm[row][c4] = v;
        }
        __syncthreads();
#pragma unroll
        for (int j = jb; j < jb + 32; j += 4) {
            float4 q0 = *(const float4*)&qsm[c][j];
            float4 q1 = *(const float4*)&qsm[c + 12][j];
            float4 k0 = *(const float4*)&ksm[d][j];
            float4 k1 = *(const float4*)&ksm[d + 12][j];
            a00 += q0.x * k0.x + q0.y * k0.y + q0.z * k0.z + q0.w * k0.w;
            a01 += q0.x * k1.x + q0.y * k1.y + q0.z * k1.z + q0.w * k1.w;
            a10 += q1.x * k0.x + q1.y * k0.y + q1.z * k0.z + q1.w * k0.w;
            a11 += q1.x * k1.x + q1.y * k1.y + q1.z * k1.z + q1.w * k1.w;
        }
    }
    float* Sp = &g_S[t][b][h][0];
    atomicAdd(&Sp[c * HD + d],             a00);
    atomicAdd(&Sp[c * HD + d + 12],        a01);
    atomicAdd(&Sp[(c + 12) * HD + d],      a10);
    atomicAdd(&Sp[(c + 12) * HD + d + 12], a11);
}

// ---------------- K4: scale + softmax + M = wproj @ blockdiag(attn) ----------------
__global__ void k4_softmax_M(const float* __restrict__ wproj,
                             const float* __restrict__ temp)
{
    int t = blockIdx.x >> 3, b = blockIdx.x & 7;
    int qs = (t == 0) ? 1 : 0;
    int kstream = 1 - qs;
    __shared__ float attn[C_IN][HD + 1];
    __shared__ float invq[C_IN], invk[C_IN];

    int tid = threadIdx.x;                 // 192 ; tid = h*HD + c
    {
        invq[tid] = 1.f / fmaxf(sqrtf(g_css[qs * 8 + b][tid]), 1e-12f);
        invk[tid] = 1.f / fmaxf(sqrtf(g_css[kstream * 8 + b][C_IN + tid]), 1e-12f);
    }
    __syncthreads();
    {
        int h = tid / HD, c = tid % HD;
        float tp = temp[h];
        float iq = invq[tid];
        float row[HD];
        float mx = -1e30f;
#pragma unroll
        for (int d = 0; d < HD; d++) {
            float v = g_S[t][b][h][c * HD + d] * iq * invk[h * HD + d] * tp;
            row[d] = v;
            mx = fmaxf(mx, v);
        }
        float sum = 0.f;
#pragma unroll
        for (int d = 0; d < HD; d++) { row[d] = expf(row[d] - mx); sum += row[d]; }
        float inv = 1.f / sum;
#pragma unroll
        for (int d = 0; d < HD; d++) attn[tid][d] = row[d] * inv;
    }
    __syncthreads();

    int o = tid;
    const float* wp = wproj + (size_t)o * C_IN;
    float* Mrow = &g_M[t][b][(size_t)o * C_IN];
    for (int h = 0; h < HEADS; h++) {
        float wreg[HD];
#pragma unroll
        for (int i = 0; i < HD; i++) wreg[i] = wp[h * HD + i];
#pragma unroll
        for (int j = 0; j < HD; j++) {
            float s = 0.f;
#pragma unroll
            for (int i = 0; i < HD; i++) s += wreg[i] * attn[h * HD + i][j];
            Mrow[h * HD + j] = s;
        }
    }
}

// ---------------- launch ----------------
extern "C" void kernel_launch(void* const* d_in, const int* in_sizes, int n_in,
                              void* d_out, int out_size)
{
    const float* rgb   = (const float*)d_in[0];
    const float* ir    = (const float*)d_in[1];
    const float* wqkv  = (const float*)d_in[2];
    const float* wdw   = (const float*)d_in[3];
    const float* wproj = (const float*)d_in[4];
    const float* temp  = (const float*)d_in[5];
    float* out = (float*)d_out;

    k0_zero<<<288, 256>>>();

    dim3 g1(HW / 128, 5, 16);     // m0: 0,128,256,384,448(clamped)
    k1_qkv<<<g1, 128>>>(rgb, ir, wqkv);

    dim3 g2(HW / 1024, C3, 16);
    k2_dw<<<g2, 256>>>(wdw);

    dim3 g3(16, NB * HEADS, 2);
    k3_gram<<<g3, 576>>>();

    k4_softmax_M<<<16, 192>>>(wproj, temp);

    dim3 g5(HW / 128, 2, 16);     // m0: 0, 64 (overlap)
    k5_out<<<g5, 128>>>(out);
}

// round 6
// speedup vs baseline: 1.1381x; 1.1381x over previous
#include <cuda_runtime.h>
#include <cuda_fp16.h>
#include <cstdint>
#include <math.h>

// ---------------- problem constants ----------------
#define HW     16384      // 128*128
#define WIMG   128
#define C_IN   192
#define C3     576        // 3*C_IN
#define NB     8
#define HEADS  8
#define HD     24

// ---------------- scratch ----------------
__device__ float g_y  [16][C3 * HW];
__device__ float g_qkv[16][C3 * HW];
__device__ float g_S  [2][NB][HEADS][HD * HD];
__device__ float g_css[16][C3];
__device__ float g_M  [2][NB][C_IN * C_IN];

// ---------------- K0: zero accumulators ----------------
__global__ void k0_zero() {
    int idx = blockIdx.x * 256 + threadIdx.x;
    const int nS = 2 * NB * HEADS * HD * HD;
    const int nC = 16 * C3;
    if (idx < nS) (&g_S[0][0][0][0])[idx] = 0.f;
    if (idx < nC) (&g_css[0][0])[idx] = 0.f;
}

// ---------------- fp16 helpers ----------------
__device__ __forceinline__ uint32_t pack2(float a, float b) {
    __half2 h = __floats2half2_rn(a, b);   // .x = a (low), .y = b (high)
    return *(uint32_t*)&h;
}
__device__ __forceinline__ void mma_16x8x16(float* c, const uint32_t* a, const uint32_t* b) {
    asm volatile(
        "mma.sync.aligned.m16n8k16.row.col.f32.f16.f16.f32 "
        "{%0,%1,%2,%3}, {%4,%5,%6,%7}, {%8,%9}, {%0,%1,%2,%3};"
        : "+f"(c[0]), "+f"(c[1]), "+f"(c[2]), "+f"(c[3])
        : "r"(a[0]), "r"(a[1]), "r"(a[2]), "r"(a[3]), "r"(b[0]), "r"(b[1]));
}

// ---------------- fp16 mma GEMM: C[m0:m0+192, n0:n0+128] = A(.,192)@B(192,HW) ----------------
// 256 threads, 8 warps (4M x 2N), warp tile 48x64 = 3x8 m16n8k16 tiles.
// BK=32 (2 k16 steps per chunk), double-buffered. 6 chunks (K=192).
__device__ __forceinline__ void gemm_mma_192x128(
    const float* __restrict__ A, const float* __restrict__ B, float* __restrict__ C,
    int m0, int n0)
{
    // As: [m][k2] half2-words, k2 = 16 per 32-k chunk, stride 20 (conflict-free frags)
    __shared__ uint32_t As[2][192][20];   // 30720 B
    // Bs: [k2][n] half2-words packing (k, k+1) per n, stride 136 (conflict-free frags)
    __shared__ uint32_t Bs[2][16][136];   // 17408 B   (total 48128 <= 49152)

    const int tid  = threadIdx.x;
    const int wid  = tid >> 5;
    const int lane = tid & 31;
    const int warp_m = wid & 3;           // 0..3 -> 48 rows each
    const int warp_n = wid >> 2;          // 0..1 -> 64 cols each
    const int lr = lane >> 2;             // 0..7
    const int lc = lane & 3;              // 0..3

    // A global load: row = ar + it*32 (it=0..5), quad q = 4 floats
    const int ar = tid >> 3;              // 0..31
    const int aq = tid & 7;               // 0..7 -> k offset aq*4
    // B global load: k-pair k2g (and k2g+8), 4 consecutive n
    const int bk2 = tid >> 5;             // 0..7
    const int bn4 = (tid & 31) * 4;       // 0..124

    const float* Ap = A + (size_t)(m0 + ar) * 192 + aq * 4;
    const float* Bp = B + (size_t)(2 * bk2) * HW + n0 + bn4;

    uint32_t au[6][2];
    uint32_t bu[2][4];

    // ---- load chunk 0 ----
#pragma unroll
    for (int it = 0; it < 6; it++) {
        float4 v = *(const float4*)(Ap + (size_t)it * 32 * 192);
        au[it][0] = pack2(v.x, v.y);
        au[it][1] = pack2(v.z, v.w);
    }
#pragma unroll
    for (int p = 0; p < 2; p++) {
        const float* bp = Bp + (size_t)p * 16 * HW;      // k2 = bk2 + p*8
        float4 r0 = *(const float4*)bp;
        float4 r1 = *(const float4*)(bp + HW);
        bu[p][0] = pack2(r0.x, r1.x);
        bu[p][1] = pack2(r0.y, r1.y);
        bu[p][2] = pack2(r0.z, r1.z);
        bu[p][3] = pack2(r0.w, r1.w);
    }
#pragma unroll
    for (int it = 0; it < 6; it++) {
        As[0][ar + it * 32][aq * 2]     = au[it][0];
        As[0][ar + it * 32][aq * 2 + 1] = au[it][1];
    }
#pragma unroll
    for (int p = 0; p < 2; p++)
        *(uint4*)&Bs[0][bk2 + p * 8][bn4] = *(uint4*)bu[p];
    __syncthreads();

    float acc[3][8][4];
#pragma unroll
    for (int i = 0; i < 3; i++)
#pragma unroll
        for (int j = 0; j < 8; j++)
#pragma unroll
            for (int q = 0; q < 4; q++) acc[i][j][q] = 0.f;

    int buf = 0;
    for (int ch = 0; ch < 6; ch++) {
        if (ch < 5) {
            const float* Apn = Ap + (ch + 1) * 32;
            const float* Bpn = Bp + (size_t)(ch + 1) * 32 * HW;
#pragma unroll
            for (int it = 0; it < 6; it++) {
                float4 v = *(const float4*)(Apn + (size_t)it * 32 * 192);
                au[it][0] = pack2(v.x, v.y);
                au[it][1] = pack2(v.z, v.w);
            }
#pragma unroll
            for (int p = 0; p < 2; p++) {
                const float* bp = Bpn + (size_t)p * 16 * HW;
                float4 r0 = *(const float4*)bp;
                float4 r1 = *(const float4*)(bp + HW);
                bu[p][0] = pack2(r0.x, r1.x);
                bu[p][1] = pack2(r0.y, r1.y);
                bu[p][2] = pack2(r0.z, r1.z);
                bu[p][3] = pack2(r0.w, r1.w);
            }
        }
#pragma unroll
        for (int kst = 0; kst < 2; kst++) {
            const int k2 = kst * 8;                     // half2-word offset: k16 step
            uint32_t afr[3][4];
#pragma unroll
            for (int mt = 0; mt < 3; mt++) {
                int rb = warp_m * 48 + mt * 16 + lr;
                afr[mt][0] = As[buf][rb][k2 + lc];
                afr[mt][1] = As[buf][rb + 8][k2 + lc];
                afr[mt][2] = As[buf][rb][k2 + 4 + lc];
                afr[mt][3] = As[buf][rb + 8][k2 + 4 + lc];
            }
#pragma unroll
            for (int nt = 0; nt < 8; nt++) {
                int nn = warp_n * 64 + nt * 8 + lr;
                uint32_t bfr[2];
                bfr[0] = Bs[buf][k2 + lc][nn];
                bfr[1] = Bs[buf][k2 + 4 + lc][nn];
#pragma unroll
                for (int mt = 0; mt < 3; mt++)
                    mma_16x8x16(acc[mt][nt], afr[mt], bfr);
            }
        }
        if (ch < 5) {
            int nb = buf ^ 1;
#pragma unroll
            for (int it = 0; it < 6; it++) {
                As[nb][ar + it * 32][aq * 2]     = au[it][0];
                As[nb][ar + it * 32][aq * 2 + 1] = au[it][1];
            }
#pragma unroll
            for (int p = 0; p < 2; p++)
                *(uint4*)&Bs[nb][bk2 + p * 8][bn4] = *(uint4*)bu[p];
            __syncthreads();
            buf = nb;
        }
    }

#pragma unroll
    for (int mt = 0; mt < 3; mt++) {
        int row = m0 + warp_m * 48 + mt * 16 + lr;
#pragma unroll
        for (int nt = 0; nt < 8; nt++) {
            int col = n0 + warp_n * 64 + nt * 8 + lc * 2;
            *(float2*)(C + (size_t)row * HW + col)       = make_float2(acc[mt][nt][0], acc[mt][nt][1]);
            *(float2*)(C + (size_t)(row + 8) * HW + col) = make_float2(acc[mt][nt][2], acc[mt][nt][3]);
        }
    }
}

// ---------------- K1: 1x1 qkv conv ----------------
__global__ void __launch_bounds__(256, 1)
k1_qkv(const float* __restrict__ rgb, const float* __restrict__ ir,
       const float* __restrict__ wqkv)
{
    int z = blockIdx.z, s = z >> 3, b = z & 7;
    const float* x = (s ? ir : rgb) + (size_t)b * C_IN * HW;
    gemm_mma_192x128(wqkv, x, g_y[z], blockIdx.y * 192, blockIdx.x * 128);
}

// ---------------- K5: out = M @ V (m = 192 exactly, single pass) ----------------
__global__ void __launch_bounds__(256, 1)
k5_out(float* __restrict__ out)
{
    int z = blockIdx.z;
    const float* A = g_M[z >> 3][z & 7];
    const float* V = g_qkv[z] + (size_t)(2 * C_IN) * HW;
    float* C = out + (size_t)z * C_IN * HW;
    gemm_mma_192x128(A, V, C, 0, blockIdx.x * 128);
}

// ---------------- K2: depthwise 3x3 SAME + per-channel sumsq ----------------
__global__ void k2_dw(const float* __restrict__ wdw)
{
    int z  = blockIdx.z;
    int ch = blockIdx.y;
    int n  = blockIdx.x * 1024 + threadIdx.x * 4;
    const float* yin = g_y[z]  + (size_t)ch * HW;
    float*       out = g_qkv[z] + (size_t)ch * HW;

    const float* w = wdw + ch * 9;
    float wr[3][3];
#pragma unroll
    for (int i = 0; i < 9; i++) wr[i / 3][i % 3] = w[i];

    int yy = n >> 7, xx = n & 127;
    bool xm = (xx > 0), xp = (xx < 124);
    float o0 = 0.f, o1 = 0.f, o2 = 0.f, o3 = 0.f;
#pragma unroll
    for (int r = 0; r < 3; r++) {
        int ry = yy + r - 1;
        if (ry < 0 || ry >= WIMG) continue;
        const float* row = yin + (size_t)ry * WIMG;
        float4 cv = *(const float4*)&row[xx];
        float lft = xm ? row[xx - 1] : 0.f;
        float rgt = xp ? row[xx + 4] : 0.f;
        float w0 = wr[r][0], w1 = wr[r][1], w2 = wr[r][2];
        o0 += w0 * lft  + w1 * cv.x + w2 * cv.y;
        o1 += w0 * cv.x + w1 * cv.y + w2 * cv.z;
        o2 += w0 * cv.y + w1 * cv.z + w2 * cv.w;
        o3 += w0 * cv.z + w1 * cv.w + w2 * rgt;
    }
    *(float4*)&out[n] = make_float4(o0, o1, o2, o3);

    float ss = o0 * o0 + o1 * o1 + o2 * o2 + o3 * o3;
#pragma unroll
    for (int off = 16; off; off >>= 1) ss += __shfl_xor_sync(0xFFFFFFFFu, ss, off);
    if ((threadIdx.x & 31) == 0) atomicAdd(&g_css[z][ch], ss);
}

// ---------------- K3: channel Gram (2x2 per thread) ----------------
__global__ void k3_gram()
{
    int t  = blockIdx.z;
    int bh = blockIdx.y;
    int b = bh >> 3, h = bh & 7;
    int n0 = blockIdx.x * 1024;

    int qs = (t == 0) ? 1 : 0;
    int kstream = 1 - qs;
    const float* qbase = g_qkv[qs * 8 + b]      + (size_t)(h * HD) * HW + n0;
    const float* kbase = g_qkv[kstream * 8 + b] + (size_t)(C_IN + h * HD) * HW + n0;

    __shared__ float qsm[HD][132];
    __shared__ float ksm[HD][132];

    int tid = threadIdx.x;                // 576 = 4 j-groups x 144
    int g = tid / 144;
    int r = tid - g * 144;
    int c = r / 12;
    int d = r - c * 12;
    const int jb = g * 32;

    float a00 = 0.f, a01 = 0.f, a10 = 0.f, a11 = 0.f;

    for (int ch0 = 0; ch0 < 1024; ch0 += 128) {
        __syncthreads();
        for (int i = tid; i < 2 * HD * 32; i += 576) {
            int arr = (i >= 768);
            int li  = arr ? (i - 768) : i;
            int row = li >> 5;
            int c4  = (li & 31) * 4;
            const float* src = arr ? kbase : qbase;
            float4 v = *(const float4*)&src[(size_t)row * HW + ch0 + c4];
            if (arr) *(float4*)&ksm[row][c4] = v;
            else     *(float4*)&qsm[row][c4] = v;
        }
        __syncthreads();
#pragma unroll
        for (int j = jb; j < jb + 32; j += 4) {
            float4 q0 = *(const float4*)&qsm[c][j];
            float4 q1 = *(const float4*)&qsm[c + 12][j];
            float4 k0 = *(const float4*)&ksm[d][j];
            float4 k1 = *(const float4*)&ksm[d + 12][j];
            a00 += q0.x * k0.x + q0.y * k0.y + q0.z * k0.z + q0.w * k0.w;
            a01 += q0.x * k1.x + q0.y * k1.y + q0.z * k1.z + q0.w * k1.w;
            a10 += q1.x * k0.x + q1.y * k0.y + q1.z * k0.z + q1.w * k0.w;
            a11 += q1.x * k1.x + q1.y * k1.y + q1.z * k1.z + q1.w * k1.w;
        }
    }
    float* Sp = &g_S[t][b][h][0];
    atomicAdd(&Sp[c * HD + d],             a00);
    atomicAdd(&Sp[c * HD + d + 12],        a01);
    atomicAdd(&Sp[(c + 12) * HD + d],      a10);
    atomicAdd(&Sp[(c + 12) * HD + d + 12], a11);
}

// ---------------- K4: scale + softmax + M = wproj @ blockdiag(attn) ----------------
__global__ void k4_softmax_M(const float* __restrict__ wproj,
                             const float* __restrict__ temp)
{
    int t = blockIdx.x >> 3, b = blockIdx.x & 7;
    int qs = (t == 0) ? 1 : 0;
    int kstream = 1 - qs;
    __shared__ float attn[C_IN][HD + 1];
    __shared__ float invq[C_IN], invk[C_IN];

    int tid = threadIdx.x;                 // 192 ; tid = h*HD + c
    {
        invq[tid] = 1.f / fmaxf(sqrtf(g_css[qs * 8 + b][tid]), 1e-12f);
        invk[tid] = 1.f / fmaxf(sqrtf(g_css[kstream * 8 + b][C_IN + tid]), 1e-12f);
    }
    __syncthreads();
    {
        int h = tid / HD, c = tid % HD;
        float tp = temp[h];
        float iq = invq[tid];
        float row[HD];
        float mx = -1e30f;
#pragma unroll
        for (int d = 0; d < HD; d++) {
            float v = g_S[t][b][h][c * HD + d] * iq * invk[h * HD + d] * tp;
            row[d] = v;
            mx = fmaxf(mx, v);
        }
        float sum = 0.f;
#pragma unroll
        for (int d = 0; d < HD; d++) { row[d] = expf(row[d] - mx); sum += row[d]; }
        float inv = 1.f / sum;
#pragma unroll
        for (int d = 0; d < HD; d++) attn[tid][d] = row[d] * inv;
    }
    __syncthreads();

    int o = tid;
    const float* wp = wproj + (size_t)o * C_IN;
    float* Mrow = &g_M[t][b][(size_t)o * C_IN];
    for (int h = 0; h < HEADS; h++) {
        float wreg[HD];
#pragma unroll
        for (int i = 0; i < HD; i++) wreg[i] = wp[h * HD + i];
#pragma unroll
        for (int j = 0; j < HD; j++) {
            float s = 0.f;
#pragma unroll
            for (int i = 0; i < HD; i++) s += wreg[i] * attn[h * HD + i][j];
            Mrow[h * HD + j] = s;
        }
    }
}

// ---------------- launch ----------------
extern "C" void kernel_launch(void* const* d_in, const int* in_sizes, int n_in,
                              void* d_out, int out_size)
{
    const float* rgb   = (const float*)d_in[0];
    const float* ir    = (const float*)d_in[1];
    const float* wqkv  = (const float*)d_in[2];
    const float* wdw   = (const float*)d_in[3];
    const float* wproj = (const float*)d_in[4];
    const float* temp  = (const float*)d_in[5];
    float* out = (float*)d_out;

    k0_zero<<<288, 256>>>();

    dim3 g1(HW / 128, 3, 16);     // m0: 0,192,384
    k1_qkv<<<g1, 256>>>(rgb, ir, wqkv);

    dim3 g2(HW / 1024, C3, 16);
    k2_dw<<<g2, 256>>>(wdw);

    dim3 g3(16, NB * HEADS, 2);
    k3_gram<<<g3, 576>>>();

    k4_softmax_M<<<16, 192>>>(wproj, temp);

    dim3 g5(HW / 128, 1, 16);     // single m pass (192 rows)
    k5_out<<<g5, 256>>>(out);
}

// round 7
// speedup vs baseline: 1.3204x; 1.1602x over previous
#include <cuda_runtime.h>
#include <cuda_fp16.h>
#include <cstdint>
#include <math.h>

// ---------------- problem constants ----------------
#define HW     16384      // 128*128
#define WIMG   128
#define C_IN   192
#define C3     576        // 3*C_IN
#define NB     8
#define HEADS  8
#define HD     24

// ---------------- scratch ----------------
__device__ __half g_y  [16][C3 * HW];   // 302 MB
__device__ __half g_qkv[16][C3 * HW];   // 302 MB
__device__ float  g_S  [2][NB][HEADS][HD * HD];
__device__ float  g_css[16][C3];
__device__ float  g_M  [2][NB][C_IN * C_IN];

// ---------------- K0: zero accumulators ----------------
__global__ void k0_zero() {
    int idx = blockIdx.x * 256 + threadIdx.x;
    const int nS = 2 * NB * HEADS * HD * HD;
    const int nC = 16 * C3;
    if (idx < nS) (&g_S[0][0][0][0])[idx] = 0.f;
    if (idx < nC) (&g_css[0][0])[idx] = 0.f;
}

// ---------------- fp16 helpers ----------------
__device__ __forceinline__ uint32_t pack2(float a, float b) {
    __half2 h = __floats2half2_rn(a, b);
    return *(uint32_t*)&h;
}
__device__ __forceinline__ uint32_t interleave_lo(uint32_t x, uint32_t y) {
    // (x.lo, y.lo)
    uint32_t r;
    asm("prmt.b32 %0, %1, %2, 0x5410;" : "=r"(r) : "r"(x), "r"(y));
    return r;
}
__device__ __forceinline__ uint32_t interleave_hi(uint32_t x, uint32_t y) {
    // (x.hi, y.hi)
    uint32_t r;
    asm("prmt.b32 %0, %1, %2, 0x7632;" : "=r"(r) : "r"(x), "r"(y));
    return r;
}
__device__ __forceinline__ void mma_16x8x16(float* c, const uint32_t* a, const uint32_t* b) {
    asm volatile(
        "mma.sync.aligned.m16n8k16.row.col.f32.f16.f16.f32 "
        "{%0,%1,%2,%3}, {%4,%5,%6,%7}, {%8,%9}, {%0,%1,%2,%3};"
        : "+f"(c[0]), "+f"(c[1]), "+f"(c[2]), "+f"(c[3])
        : "r"(a[0]), "r"(a[1]), "r"(a[2]), "r"(a[3]), "r"(b[0]), "r"(b[1]));
}

// ---------------- fp16 mma GEMM: C[m0:m0+192, n0:n0+128] = A(.,192)@B(192,HW) ----------------
// 256 threads, 8 warps (4M x 2N), warp tile 48x64. BK=32, double-buffered, 6 chunks.
// B_HALF: B source is __half (else float). C_HALF: C dest is __half (else float).
template<bool B_HALF, bool C_HALF>
__device__ __forceinline__ void gemm_mma_192x128(
    const float* __restrict__ A, const void* __restrict__ Bv, void* __restrict__ Cv,
    int m0, int n0)
{
    __shared__ uint32_t As[2][192][20];   // [m][k2] half2 words
    __shared__ uint32_t Bs[2][16][136];   // [k2][n] half2 words packing (k,k+1)

    const int tid  = threadIdx.x;
    const int wid  = tid >> 5;
    const int lane = tid & 31;
    const int warp_m = wid & 3;
    const int warp_n = wid >> 2;
    const int lr = lane >> 2;
    const int lc = lane & 3;

    const int ar = tid >> 3;              // 0..31
    const int aq = tid & 7;               // k offset aq*4
    const int bk2 = tid >> 5;             // 0..7
    const int bn4 = (tid & 31) * 4;       // 0..124

    const float* Ap = A + (size_t)(m0 + ar) * 192 + aq * 4;
    const float*  Bpf = B_HALF ? nullptr : ((const float*)Bv + (size_t)(2 * bk2) * HW + n0 + bn4);
    const __half* Bph = B_HALF ? ((const __half*)Bv + (size_t)(2 * bk2) * HW + n0 + bn4) : nullptr;

    uint32_t au[6][2];
    uint32_t bu[2][4];

    auto loadB = [&](int ch) {
#pragma unroll
        for (int p = 0; p < 2; p++) {
            if (B_HALF) {
                const __half* bp = Bph + (size_t)(ch * 32 + p * 16) * HW;
                uint2 r0 = *(const uint2*)bp;
                uint2 r1 = *(const uint2*)(bp + HW);
                bu[p][0] = interleave_lo(r0.x, r1.x);
                bu[p][1] = interleave_hi(r0.x, r1.x);
                bu[p][2] = interleave_lo(r0.y, r1.y);
                bu[p][3] = interleave_hi(r0.y, r1.y);
            } else {
                const float* bp = Bpf + (size_t)(ch * 32 + p * 16) * HW;
                float4 r0 = *(const float4*)bp;
                float4 r1 = *(const float4*)(bp + HW);
                bu[p][0] = pack2(r0.x, r1.x);
                bu[p][1] = pack2(r0.y, r1.y);
                bu[p][2] = pack2(r0.z, r1.z);
                bu[p][3] = pack2(r0.w, r1.w);
            }
        }
    };
    auto loadA = [&](int ch) {
#pragma unroll
        for (int it = 0; it < 6; it++) {
            float4 v = *(const float4*)(Ap + ch * 32 + (size_t)it * 32 * 192);
            au[it][0] = pack2(v.x, v.y);
            au[it][1] = pack2(v.z, v.w);
        }
    };
    auto stage = [&](int nb) {
#pragma unroll
        for (int it = 0; it < 6; it++) {
            As[nb][ar + it * 32][aq * 2]     = au[it][0];
            As[nb][ar + it * 32][aq * 2 + 1] = au[it][1];
        }
#pragma unroll
        for (int p = 0; p < 2; p++)
            *(uint4*)&Bs[nb][bk2 + p * 8][bn4] = *(uint4*)bu[p];
    };

    loadA(0); loadB(0);
    stage(0);
    __syncthreads();

    float acc[3][8][4];
#pragma unroll
    for (int i = 0; i < 3; i++)
#pragma unroll
        for (int j = 0; j < 8; j++)
#pragma unroll
            for (int q = 0; q < 4; q++) acc[i][j][q] = 0.f;

    int buf = 0;
    for (int ch = 0; ch < 6; ch++) {
        if (ch < 5) { loadA(ch + 1); loadB(ch + 1); }
#pragma unroll
        for (int kst = 0; kst < 2; kst++) {
            const int k2 = kst * 8;
            uint32_t afr[3][4];
#pragma unroll
            for (int mt = 0; mt < 3; mt++) {
                int rb = warp_m * 48 + mt * 16 + lr;
                afr[mt][0] = As[buf][rb][k2 + lc];
                afr[mt][1] = As[buf][rb + 8][k2 + lc];
                afr[mt][2] = As[buf][rb][k2 + 4 + lc];
                afr[mt][3] = As[buf][rb + 8][k2 + 4 + lc];
            }
#pragma unroll
            for (int nt = 0; nt < 8; nt++) {
                int nn = warp_n * 64 + nt * 8 + lr;
                uint32_t bfr[2];
                bfr[0] = Bs[buf][k2 + lc][nn];
                bfr[1] = Bs[buf][k2 + 4 + lc][nn];
#pragma unroll
                for (int mt = 0; mt < 3; mt++)
                    mma_16x8x16(acc[mt][nt], afr[mt], bfr);
            }
        }
        if (ch < 5) {
            int nb = buf ^ 1;
            stage(nb);
            __syncthreads();
            buf = nb;
        }
    }

#pragma unroll
    for (int mt = 0; mt < 3; mt++) {
        int row = m0 + warp_m * 48 + mt * 16 + lr;
#pragma unroll
        for (int nt = 0; nt < 8; nt++) {
            int col = n0 + warp_n * 64 + nt * 8 + lc * 2;
            if (C_HALF) {
                __half* Ch = (__half*)Cv;
                *(uint32_t*)(Ch + (size_t)row * HW + col)       = pack2(acc[mt][nt][0], acc[mt][nt][1]);
                *(uint32_t*)(Ch + (size_t)(row + 8) * HW + col) = pack2(acc[mt][nt][2], acc[mt][nt][3]);
            } else {
                float* Cf = (float*)Cv;
                *(float2*)(Cf + (size_t)row * HW + col)       = make_float2(acc[mt][nt][0], acc[mt][nt][1]);
                *(float2*)(Cf + (size_t)(row + 8) * HW + col) = make_float2(acc[mt][nt][2], acc[mt][nt][3]);
            }
        }
    }
}

// ---------------- K1: 1x1 qkv conv (B fp32 in, C fp16 out) ----------------
__global__ void __launch_bounds__(256, 1)
k1_qkv(const float* __restrict__ rgb, const float* __restrict__ ir,
       const float* __restrict__ wqkv)
{
    int z = blockIdx.z, s = z >> 3, b = z & 7;
    const float* x = (s ? ir : rgb) + (size_t)b * C_IN * HW;
    gemm_mma_192x128<false, true>(wqkv, x, g_y[z], blockIdx.y * 192, blockIdx.x * 128);
}

// ---------------- K5: out = M @ V (B fp16 in, C fp32 out) ----------------
__global__ void __launch_bounds__(256, 1)
k5_out(float* __restrict__ out)
{
    int z = blockIdx.z;
    const float* A = g_M[z >> 3][z & 7];
    const __half* V = g_qkv[z] + (size_t)(2 * C_IN) * HW;
    float* C = out + (size_t)z * C_IN * HW;
    gemm_mma_192x128<true, false>(A, V, C, 0, blockIdx.x * 128);
}

// ---------------- K2: depthwise 3x3 SAME (half IO) + per-channel sumsq ----------------
__global__ void k2_dw(const float* __restrict__ wdw)
{
    int z  = blockIdx.z;
    int ch = blockIdx.y;
    int n  = blockIdx.x * 1024 + threadIdx.x * 4;
    const __half* yin = g_y[z]  + (size_t)ch * HW;
    __half*       out = g_qkv[z] + (size_t)ch * HW;

    const float* w = wdw + ch * 9;
    float wr[3][3];
#pragma unroll
    for (int i = 0; i < 9; i++) wr[i / 3][i % 3] = w[i];

    int yy = n >> 7, xx = n & 127;
    bool xm = (xx > 0), xp = (xx < 124);
    float o0 = 0.f, o1 = 0.f, o2 = 0.f, o3 = 0.f;
#pragma unroll
    for (int r = 0; r < 3; r++) {
        int ry = yy + r - 1;
        if (ry < 0 || ry >= WIMG) continue;
        const __half* row = yin + (size_t)ry * WIMG;
        uint2 cvu = *(const uint2*)&row[xx];
        float2 c01 = __half22float2(*(__half2*)&cvu.x);
        float2 c23 = __half22float2(*(__half2*)&cvu.y);
        float lft = xm ? __half2float(row[xx - 1]) : 0.f;
        float rgt = xp ? __half2float(row[xx + 4]) : 0.f;
        float w0 = wr[r][0], w1 = wr[r][1], w2 = wr[r][2];
        o0 += w0 * lft   + w1 * c01.x + w2 * c01.y;
        o1 += w0 * c01.x + w1 * c01.y + w2 * c23.x;
        o2 += w0 * c01.y + w1 * c23.x + w2 * c23.y;
        o3 += w0 * c23.x + w1 * c23.y + w2 * rgt;
    }
    uint2 ov;
    ov.x = pack2(o0, o1);
    ov.y = pack2(o2, o3);
    *(uint2*)&out[n] = ov;

    float ss = o0 * o0 + o1 * o1 + o2 * o2 + o3 * o3;
#pragma unroll
    for (int off = 16; off; off >>= 1) ss += __shfl_xor_sync(0xFFFFFFFFu, ss, off);
    if ((threadIdx.x & 31) == 0) atomicAdd(&g_css[z][ch], ss);
}

// ---------------- K3: channel Gram via tensor cores ----------------
// Block: 256 threads, one (t,b,h), K-slice of 2048 (8 chunks of 256).
// 8 warps each own 32 K within a chunk (2 k16 steps). Output 32x24 (rows>=24 discarded).
__global__ void __launch_bounds__(256)
k3_gram()
{
    __shared__ __align__(16) char smraw[16896 + 12672];  // qsm[32][132] + ksm[24][132] half2
    __half2 (*qsm)[132] = reinterpret_cast<__half2(*)[132]>(smraw);
    __half2 (*ksm)[132] = reinterpret_cast<__half2(*)[132]>(smraw + 16896);
    float* red = reinterpret_cast<float*>(smraw);        // overlay: 8*576 floats = 18432 B

    int t  = blockIdx.z;
    int bh = blockIdx.y;
    int b = bh >> 3, h = bh & 7;
    int n0 = blockIdx.x * 2048;

    int qs = (t == 0) ? 1 : 0;
    int kstream = 1 - qs;
    const __half* qb = g_qkv[qs * 8 + b]      + (size_t)(h * HD) * HW + n0;
    const __half* kb = g_qkv[kstream * 8 + b] + (size_t)(C_IN + h * HD) * HW + n0;

    const int tid  = threadIdx.x;
    const int wid  = tid >> 5;
    const int lane = tid & 31;
    const int lr = lane >> 2;
    const int lc = lane & 3;
    const int kw = wid * 16;              // word offset of this warp's 32-k range

    float acc[2][3][4];
#pragma unroll
    for (int i = 0; i < 2; i++)
#pragma unroll
        for (int j = 0; j < 3; j++)
#pragma unroll
            for (int q = 0; q < 4; q++) acc[i][j][q] = 0.f;

    for (int c0 = 0; c0 < 2048; c0 += 256) {
        __syncthreads();
        // load q[24][256] and k[24][256] halfs (1536 uint4)
        for (int i = tid; i < 1536; i += 256) {
            int arr = (i >= 768);
            int li  = arr ? (i - 768) : i;
            int row = li >> 5;            // 0..23
            int v8  = (li & 31) * 8;      // half offset
            const __half* src = arr ? kb : qb;
            uint4 v = *(const uint4*)&src[(size_t)row * HW + c0 + v8];
            if (arr) *(uint4*)&ksm[row][v8 >> 1] = v;
            else     *(uint4*)&qsm[row][v8 >> 1] = v;
        }
        __syncthreads();
#pragma unroll
        for (int kst = 0; kst < 2; kst++) {
            const int ko = kw + kst * 8;
            uint32_t afr[2][4];
#pragma unroll
            for (int mt = 0; mt < 2; mt++) {
                int rb = mt * 16 + lr;
                afr[mt][0] = *(uint32_t*)&qsm[rb][ko + lc];
                afr[mt][1] = *(uint32_t*)&qsm[rb + 8][ko + lc];
                afr[mt][2] = *(uint32_t*)&qsm[rb][ko + 4 + lc];
                afr[mt][3] = *(uint32_t*)&qsm[rb + 8][ko + 4 + lc];
            }
#pragma unroll
            for (int nt = 0; nt < 3; nt++) {
                uint32_t bfr[2];
                bfr[0] = *(uint32_t*)&ksm[nt * 8 + lr][ko + lc];
                bfr[1] = *(uint32_t*)&ksm[nt * 8 + lr][ko + 4 + lc];
#pragma unroll
                for (int mt = 0; mt < 2; mt++)
                    mma_16x8x16(acc[mt][nt], afr[mt], bfr);
            }
        }
    }
    __syncthreads();   // done with qsm/ksm; reuse as reduction buffer

    float* rw = red + wid * 576;
#pragma unroll
    for (int mt = 0; mt < 2; mt++) {
        int r0 = mt * 16 + lr;
#pragma unroll
        for (int nt = 0; nt < 3; nt++) {
            int cc = nt * 8 + lc * 2;
            rw[r0 * 24 + cc]     = acc[mt][nt][0];
            rw[r0 * 24 + cc + 1] = acc[mt][nt][1];
            if (mt == 0) {
                rw[(r0 + 8) * 24 + cc]     = acc[mt][nt][2];
                rw[(r0 + 8) * 24 + cc + 1] = acc[mt][nt][3];
            }
        }
    }
    __syncthreads();

    float* Sp = &g_S[t][b][h][0];
    for (int i = tid; i < 576; i += 256) {
        float s = 0.f;
#pragma unroll
        for (int w = 0; w < 8; w++) s += red[w * 576 + i];
        atomicAdd(&Sp[i], s);
    }
}

// ---------------- K4: scale + softmax + M = wproj @ blockdiag(attn) ----------------
__global__ void k4_softmax_M(const float* __restrict__ wproj,
                             const float* __restrict__ temp)
{
    int t = blockIdx.x >> 3, b = blockIdx.x & 7;
    int qs = (t == 0) ? 1 : 0;
    int kstream = 1 - qs;
    __shared__ float attn[C_IN][HD + 1];
    __shared__ float invq[C_IN], invk[C_IN];

    int tid = threadIdx.x;                 // 192 ; tid = h*HD + c
    {
        invq[tid] = 1.f / fmaxf(sqrtf(g_css[qs * 8 + b][tid]), 1e-12f);
        invk[tid] = 1.f / fmaxf(sqrtf(g_css[kstream * 8 + b][C_IN + tid]), 1e-12f);
    }
    __syncthreads();
    {
        int h = tid / HD, c = tid % HD;
        float tp = temp[h];
        float iq = invq[tid];
        float row[HD];
        float mx = -1e30f;
#pragma unroll
        for (int d = 0; d < HD; d++) {
            float v = g_S[t][b][h][c * HD + d] * iq * invk[h * HD + d] * tp;
            row[d] = v;
            mx = fmaxf(mx, v);
        }
        float sum = 0.f;
#pragma unroll
        for (int d = 0; d < HD; d++) { row[d] = expf(row[d] - mx); sum += row[d]; }
        float inv = 1.f / sum;
#pragma unroll
        for (int d = 0; d < HD; d++) attn[tid][d] = row[d] * inv;
    }
    __syncthreads();

    int o = tid;
    const float* wp = wproj + (size_t)o * C_IN;
    float* Mrow = &g_M[t][b][(size_t)o * C_IN];
    for (int h = 0; h < HEADS; h++) {
        float wreg[HD];
#pragma unroll
        for (int i = 0; i < HD; i++) wreg[i] = wp[h * HD + i];
#pragma unroll
        for (int j = 0; j < HD; j++) {
            float s = 0.f;
#pragma unroll
            for (int i = 0; i < HD; i++) s += wreg[i] * attn[h * HD + i][j];
            Mrow[h * HD + j] = s;
        }
    }
}

// ---------------- launch ----------------
extern "C" void kernel_launch(void* const* d_in, const int* in_sizes, int n_in,
                              void* d_out, int out_size)
{
    const float* rgb   = (const float*)d_in[0];
    const float* ir    = (const float*)d_in[1];
    const float* wqkv  = (const float*)d_in[2];
    const float* wdw   = (const float*)d_in[3];
    const float* wproj = (const float*)d_in[4];
    const float* temp  = (const float*)d_in[5];
    float* out = (float*)d_out;

    k0_zero<<<288, 256>>>();

    dim3 g1(HW / 128, 3, 16);     // m0: 0,192,384
    k1_qkv<<<g1, 256>>>(rgb, ir, wqkv);

    dim3 g2(HW / 1024, C3, 16);
    k2_dw<<<g2, 256>>>(wdw);

    dim3 g3(8, NB * HEADS, 2);    // K-slices of 2048
    k3_gram<<<g3, 256>>>();

    k4_softmax_M<<<16, 192>>>(wproj, temp);

    dim3 g5(HW / 128, 1, 16);     // single m pass (192 rows)
    k5_out<<<g5, 256>>>(out);
}

// round 8
// speedup vs baseline: 1.5860x; 1.2011x over previous
#include <cuda_runtime.h>
#include <cuda_fp16.h>
#include <cstdint>
#include <math.h>

// ---------------- problem constants ----------------
#define HW     16384      // 128*128
#define WIMG   128
#define C_IN   192
#define C3     576        // 3*C_IN
#define NB     8
#define HEADS  8
#define HD     24

// ---------------- scratch ----------------
__device__ __half g_y  [16][C3 * HW];
__device__ __half g_qkv[16][C3 * HW];
__device__ float  g_S  [2][NB][HEADS][HD * HD];
__device__ float  g_css[16][C3];
__device__ float  g_M  [2][NB][C_IN * C_IN];

// ---------------- K0: zero accumulators ----------------
__global__ void k0_zero() {
    int idx = blockIdx.x * 256 + threadIdx.x;
    const int nS = 2 * NB * HEADS * HD * HD;
    const int nC = 16 * C3;
    if (idx < nS) (&g_S[0][0][0][0])[idx] = 0.f;
    if (idx < nC) (&g_css[0][0])[idx] = 0.f;
}

// ---------------- fp16 / mma helpers ----------------
__device__ __forceinline__ uint32_t pack2(float a, float b) {
    __half2 h = __floats2half2_rn(a, b);
    return *(uint32_t*)&h;
}
__device__ __forceinline__ uint32_t interleave_lo(uint32_t x, uint32_t y) {
    uint32_t r;
    asm("prmt.b32 %0, %1, %2, 0x5410;" : "=r"(r) : "r"(x), "r"(y));
    return r;
}
__device__ __forceinline__ uint32_t interleave_hi(uint32_t x, uint32_t y) {
    uint32_t r;
    asm("prmt.b32 %0, %1, %2, 0x7632;" : "=r"(r) : "r"(x), "r"(y));
    return r;
}
__device__ __forceinline__ void mma_16x8x16(float* c, const uint32_t* a, const uint32_t* b) {
    asm volatile(
        "mma.sync.aligned.m16n8k16.row.col.f32.f16.f16.f32 "
        "{%0,%1,%2,%3}, {%4,%5,%6,%7}, {%8,%9}, {%0,%1,%2,%3};"
        : "+f"(c[0]), "+f"(c[1]), "+f"(c[2]), "+f"(c[3])
        : "r"(a[0]), "r"(a[1]), "r"(a[2]), "r"(a[3]), "r"(b[0]), "r"(b[1]));
}
__device__ __forceinline__ void ldmx4(uint32_t* r, uint32_t addr) {
    asm volatile("ldmatrix.sync.aligned.m8n8.x4.shared.b16 {%0,%1,%2,%3}, [%4];"
        : "=r"(r[0]), "=r"(r[1]), "=r"(r[2]), "=r"(r[3]) : "r"(addr));
}
__device__ __forceinline__ void ldmx2(uint32_t* r, uint32_t addr) {
    asm volatile("ldmatrix.sync.aligned.m8n8.x2.shared.b16 {%0,%1}, [%2];"
        : "=r"(r[0]), "=r"(r[1]) : "r"(addr));
}
__device__ __forceinline__ uint32_t sh_addr(const void* p) {
    return (uint32_t)__cvta_generic_to_shared(p);
}

// ---------------- fp16 mma GEMM: C[m0:m0+192, n0:n0+128] ----------------
// 256 threads, 8 warps (4M x 2N), warp tile 48x64. BK=32, double-buffered, 6 chunks.
template<bool B_HALF, bool C_HALF>
__device__ __forceinline__ void gemm_mma_192x128(
    const float* __restrict__ A, const void* __restrict__ Bv, void* __restrict__ Cv,
    int m0, int n0)
{
    __shared__ uint32_t As[2][192][20];   // [m][k2]
    __shared__ uint32_t Bs[2][16][136];   // [k2][n] packing (k,k+1)

    const int tid  = threadIdx.x;
    const int wid  = tid >> 5;
    const int lane = tid & 31;
    const int warp_m = wid & 3;
    const int warp_n = wid >> 2;
    const int lr = lane >> 2;
    const int lc = lane & 3;

    const int ar = tid >> 3;
    const int aq = tid & 7;
    const int bk2 = tid >> 5;
    const int bn4 = (tid & 31) * 4;

    const float* Ap = A + (size_t)(m0 + ar) * 192 + aq * 4;
    const float*  Bpf = B_HALF ? nullptr : ((const float*)Bv + (size_t)(2 * bk2) * HW + n0 + bn4);
    const __half* Bph = B_HALF ? ((const __half*)Bv + (size_t)(2 * bk2) * HW + n0 + bn4) : nullptr;

    // ldmatrix per-lane offset for A tiles
    const int lg = lane >> 3;
    const int lrow = lane & 7;
    const uint32_t a_lane_off = (uint32_t)((((lg & 1) << 3) + lrow) * 20 + ((lg >> 1) << 2)) * 4;
    const uint32_t As0 = sh_addr(&As[0][0][0]);
    const uint32_t As1 = sh_addr(&As[1][0][0]);

    uint32_t au[6][2];
    uint32_t bu[2][4];

    auto loadB = [&](int ch) {
#pragma unroll
        for (int p = 0; p < 2; p++) {
            if (B_HALF) {
                const __half* bp = Bph + (size_t)(ch * 32 + p * 16) * HW;
                uint2 r0 = *(const uint2*)bp;
                uint2 r1 = *(const uint2*)(bp + HW);
                bu[p][0] = interleave_lo(r0.x, r1.x);
                bu[p][1] = interleave_hi(r0.x, r1.x);
                bu[p][2] = interleave_lo(r0.y, r1.y);
                bu[p][3] = interleave_hi(r0.y, r1.y);
            } else {
                const float* bp = Bpf + (size_t)(ch * 32 + p * 16) * HW;
                float4 r0 = *(const float4*)bp;
                float4 r1 = *(const float4*)(bp + HW);
                bu[p][0] = pack2(r0.x, r1.x);
                bu[p][1] = pack2(r0.y, r1.y);
                bu[p][2] = pack2(r0.z, r1.z);
                bu[p][3] = pack2(r0.w, r1.w);
            }
        }
    };
    auto loadA = [&](int ch) {
#pragma unroll
        for (int it = 0; it < 6; it++) {
            float4 v = *(const float4*)(Ap + ch * 32 + (size_t)it * 32 * 192);
            au[it][0] = pack2(v.x, v.y);
            au[it][1] = pack2(v.z, v.w);
        }
    };
    auto stage = [&](int nb) {
#pragma unroll
        for (int it = 0; it < 6; it++) {
            As[nb][ar + it * 32][aq * 2]     = au[it][0];
            As[nb][ar + it * 32][aq * 2 + 1] = au[it][1];
        }
#pragma unroll
        for (int p = 0; p < 2; p++)
            *(uint4*)&Bs[nb][bk2 + p * 8][bn4] = *(uint4*)bu[p];
    };

    loadA(0); loadB(0);
    stage(0);
    __syncthreads();

    float acc[3][8][4];
#pragma unroll
    for (int i = 0; i < 3; i++)
#pragma unroll
        for (int j = 0; j < 8; j++)
#pragma unroll
            for (int q = 0; q < 4; q++) acc[i][j][q] = 0.f;

    int buf = 0;
    for (int ch = 0; ch < 6; ch++) {
        if (ch < 5) { loadA(ch + 1); loadB(ch + 1); }
        const uint32_t Asb = (buf ? As1 : As0) + a_lane_off;
#pragma unroll
        for (int kst = 0; kst < 2; kst++) {
            const int k2 = kst * 8;
            uint32_t afr[3][4];
#pragma unroll
            for (int mt = 0; mt < 3; mt++)
                ldmx4(afr[mt], Asb + (uint32_t)(((warp_m * 48 + mt * 16) * 20 + k2) * 4));
#pragma unroll
            for (int nt = 0; nt < 8; nt++) {
                int nn = warp_n * 64 + nt * 8 + lr;
                uint32_t bfr[2];
                bfr[0] = Bs[buf][k2 + lc][nn];
                bfr[1] = Bs[buf][k2 + 4 + lc][nn];
#pragma unroll
                for (int mt = 0; mt < 3; mt++)
                    mma_16x8x16(acc[mt][nt], afr[mt], bfr);
            }
        }
        if (ch < 5) {
            int nb = buf ^ 1;
            stage(nb);
            __syncthreads();
            buf = nb;
        }
    }

#pragma unroll
    for (int mt = 0; mt < 3; mt++) {
        int row = m0 + warp_m * 48 + mt * 16 + lr;
#pragma unroll
        for (int nt = 0; nt < 8; nt++) {
            int col = n0 + warp_n * 64 + nt * 8 + lc * 2;
            if (C_HALF) {
                __half* Ch = (__half*)Cv;
                *(uint32_t*)(Ch + (size_t)row * HW + col)       = pack2(acc[mt][nt][0], acc[mt][nt][1]);
                *(uint32_t*)(Ch + (size_t)(row + 8) * HW + col) = pack2(acc[mt][nt][2], acc[mt][nt][3]);
            } else {
                float* Cf = (float*)Cv;
                *(float2*)(Cf + (size_t)row * HW + col)       = make_float2(acc[mt][nt][0], acc[mt][nt][1]);
                *(float2*)(Cf + (size_t)(row + 8) * HW + col) = make_float2(acc[mt][nt][2], acc[mt][nt][3]);
            }
        }
    }
}

// ---------------- K1: 1x1 qkv conv ----------------
__global__ void __launch_bounds__(256, 1)
k1_qkv(const float* __restrict__ rgb, const float* __restrict__ ir,
       const float* __restrict__ wqkv)
{
    int z = blockIdx.z, s = z >> 3, b = z & 7;
    const float* x = (s ? ir : rgb) + (size_t)b * C_IN * HW;
    gemm_mma_192x128<false, true>(wqkv, x, g_y[z], blockIdx.y * 192, blockIdx.x * 128);
}

// ---------------- K5: out = M @ V ----------------
__global__ void __launch_bounds__(256, 1)
k5_out(float* __restrict__ out)
{
    int z = blockIdx.z;
    const float* A = g_M[z >> 3][z & 7];
    const __half* V = g_qkv[z] + (size_t)(2 * C_IN) * HW;
    float* C = out + (size_t)z * C_IN * HW;
    gemm_mma_192x128<true, false>(A, V, C, 0, blockIdx.x * 128);
}

// ---------------- K2: depthwise 3x3 SAME, 8 px/thread + sumsq ----------------
__global__ void k2_dw(const float* __restrict__ wdw)
{
    int z  = blockIdx.z;
    int ch = blockIdx.y;
    int n  = blockIdx.x * 2048 + threadIdx.x * 8;
    const __half* yin = g_y[z]  + (size_t)ch * HW;
    __half*       out = g_qkv[z] + (size_t)ch * HW;

    const float* w = wdw + ch * 9;
    float wr[3][3];
#pragma unroll
    for (int i = 0; i < 9; i++) wr[i / 3][i % 3] = w[i];

    int yy = n >> 7, xx = n & 127;
    bool xm = (xx > 0), xp = (xx < 120);

    float f[3][10];
#pragma unroll
    for (int r = 0; r < 3; r++) {
        int ry = yy + r - 1;
        if (ry < 0 || ry >= WIMG) {
#pragma unroll
            for (int i = 0; i < 10; i++) f[r][i] = 0.f;
            continue;
        }
        const __half* row = yin + (size_t)ry * WIMG;
        uint4 v = *(const uint4*)&row[xx];
        float2 p0 = __half22float2(*(__half2*)&v.x);
        float2 p1 = __half22float2(*(__half2*)&v.y);
        float2 p2 = __half22float2(*(__half2*)&v.z);
        float2 p3 = __half22float2(*(__half2*)&v.w);
        f[r][1] = p0.x; f[r][2] = p0.y; f[r][3] = p1.x; f[r][4] = p1.y;
        f[r][5] = p2.x; f[r][6] = p2.y; f[r][7] = p3.x; f[r][8] = p3.y;
        f[r][0] = xm ? __half2float(row[xx - 1]) : 0.f;
        f[r][9] = xp ? __half2float(row[xx + 8]) : 0.f;
    }

    float o[8];
    float ss = 0.f;
#pragma unroll
    for (int i = 0; i < 8; i++) {
        float acc = 0.f;
#pragma unroll
        for (int r = 0; r < 3; r++)
            acc += wr[r][0] * f[r][i] + wr[r][1] * f[r][i + 1] + wr[r][2] * f[r][i + 2];
        o[i] = acc;
        ss += acc * acc;
    }
    uint4 ov;
    ov.x = pack2(o[0], o[1]);
    ov.y = pack2(o[2], o[3]);
    ov.z = pack2(o[4], o[5]);
    ov.w = pack2(o[6], o[7]);
    *(uint4*)&out[n] = ov;

#pragma unroll
    for (int off = 16; off; off >>= 1) ss += __shfl_xor_sync(0xFFFFFFFFu, ss, off);
    if ((threadIdx.x & 31) == 0) atomicAdd(&g_css[z][ch], ss);
}

// ---------------- K3: channel Gram via tensor cores + ldmatrix ----------------
__global__ void __launch_bounds__(256)
k3_gram()
{
    __shared__ __align__(16) char smraw[16896 + 12672];  // qsm[32][132] + ksm[24][132] half2
    __half2 (*qsm)[132] = reinterpret_cast<__half2(*)[132]>(smraw);
    __half2 (*ksm)[132] = reinterpret_cast<__half2(*)[132]>(smraw + 16896);
    float* red = reinterpret_cast<float*>(smraw);

    int t  = blockIdx.z;
    int bh = blockIdx.y;
    int b = bh >> 3, h = bh & 7;
    int n0 = blockIdx.x * 2048;

    int qs = (t == 0) ? 1 : 0;
    int kstream = 1 - qs;
    const __half* qb = g_qkv[qs * 8 + b]      + (size_t)(h * HD) * HW + n0;
    const __half* kb = g_qkv[kstream * 8 + b] + (size_t)(C_IN + h * HD) * HW + n0;

    const int tid  = threadIdx.x;
    const int wid  = tid >> 5;
    const int lane = tid & 31;
    const int kw = wid * 16;

    // ldmatrix lane offsets
    const int lg = lane >> 3;
    const int lrow = lane & 7;
    const uint32_t q_lane_off = (uint32_t)((((lg & 1) << 3) + lrow) * 132 + ((lg >> 1) << 2)) * 4;
    const uint32_t k_lane_off = (uint32_t)(((lane & 15) & 7) * 132 + (((lane & 15) >> 3) << 2)) * 4;
    const uint32_t qbase = sh_addr(&qsm[0][0]);
    const uint32_t kbase = sh_addr(&ksm[0][0]);

    float acc[2][3][4];
#pragma unroll
    for (int i = 0; i < 2; i++)
#pragma unroll
        for (int j = 0; j < 3; j++)
#pragma unroll
            for (int q = 0; q < 4; q++) acc[i][j][q] = 0.f;

    for (int c0 = 0; c0 < 2048; c0 += 256) {
        __syncthreads();
        for (int i = tid; i < 1536; i += 256) {
            int arr = (i >= 768);
            int li  = arr ? (i - 768) : i;
            int row = li >> 5;
            int v8  = (li & 31) * 8;
            const __half* src = arr ? kb : qb;
            uint4 v = *(const uint4*)&src[(size_t)row * HW + c0 + v8];
            if (arr) *(uint4*)&ksm[row][v8 >> 1] = v;
            else     *(uint4*)&qsm[row][v8 >> 1] = v;
        }
        __syncthreads();
#pragma unroll
        for (int kst = 0; kst < 2; kst++) {
            const int ko = kw + kst * 8;
            uint32_t afr[2][4];
#pragma unroll
            for (int mt = 0; mt < 2; mt++)
                ldmx4(afr[mt], qbase + q_lane_off + (uint32_t)((mt * 16 * 132 + ko) * 4));
#pragma unroll
            for (int nt = 0; nt < 3; nt++) {
                uint32_t bfr[2];
                ldmx2(bfr, kbase + k_lane_off + (uint32_t)((nt * 8 * 132 + ko) * 4));
#pragma unroll
                for (int mt = 0; mt < 2; mt++)
                    mma_16x8x16(acc[mt][nt], afr[mt], bfr);
            }
        }
    }
    __syncthreads();

    const int lr = lane >> 2;
    const int lc = lane & 3;
    float* rw = red + wid * 576;
#pragma unroll
    for (int mt = 0; mt < 2; mt++) {
        int r0 = mt * 16 + lr;
#pragma unroll
        for (int nt = 0; nt < 3; nt++) {
            int cc = nt * 8 + lc * 2;
            rw[r0 * 24 + cc]     = acc[mt][nt][0];
            rw[r0 * 24 + cc + 1] = acc[mt][nt][1];
            if (mt == 0) {
                rw[(r0 + 8) * 24 + cc]     = acc[mt][nt][2];
                rw[(r0 + 8) * 24 + cc + 1] = acc[mt][nt][3];
            }
        }
    }
    __syncthreads();

    float* Sp = &g_S[t][b][h][0];
    for (int i = tid; i < 576; i += 256) {
        float s = 0.f;
#pragma unroll
        for (int w = 0; w < 8; w++) s += red[w * 576 + i];
        atomicAdd(&Sp[i], s);
    }
}

// ---------------- K4: scale + softmax + M = wproj @ blockdiag(attn) ----------------
__global__ void k4_softmax_M(const float* __restrict__ wproj,
                             const float* __restrict__ temp)
{
    int t = blockIdx.x >> 3, b = blockIdx.x & 7;
    int qs = (t == 0) ? 1 : 0;
    int kstream = 1 - qs;
    __shared__ float attn[C_IN][HD + 1];
    __shared__ float invq[C_IN], invk[C_IN];

    int tid = threadIdx.x;                 // 192 ; tid = h*HD + c
    {
        invq[tid] = 1.f / fmaxf(sqrtf(g_css[qs * 8 + b][tid]), 1e-12f);
        invk[tid] = 1.f / fmaxf(sqrtf(g_css[kstream * 8 + b][C_IN + tid]), 1e-12f);
    }
    __syncthreads();
    {
        int h = tid / HD, c = tid % HD;
        float tp = temp[h];
        float iq = invq[tid];
        float row[HD];
        float mx = -1e30f;
#pragma unroll
        for (int d = 0; d < HD; d++) {
            float v = g_S[t][b][h][c * HD + d] * iq * invk[h * HD + d] * tp;
            row[d] = v;
            mx = fmaxf(mx, v);
        }
        float sum = 0.f;
#pragma unroll
        for (int d = 0; d < HD; d++) { row[d] = expf(row[d] - mx); sum += row[d]; }
        float inv = 1.f / sum;
#pragma unroll
        for (int d = 0; d < HD; d++) attn[tid][d] = row[d] * inv;
    }
    __syncthreads();

    int o = tid;
    const float* wp = wproj + (size_t)o * C_IN;
    float* Mrow = &g_M[t][b][(size_t)o * C_IN];
    for (int h = 0; h < HEADS; h++) {
        float wreg[HD];
#pragma unroll
        for (int i = 0; i < HD; i++) wreg[i] = wp[h * HD + i];
#pragma unroll
        for (int j = 0; j < HD; j++) {
            float s = 0.f;
#pragma unroll
            for (int i = 0; i < HD; i++) s += wreg[i] * attn[h * HD + i][j];
            Mrow[h * HD + j] = s;
        }
    }
}

// ---------------- launch ----------------
extern "C" void kernel_launch(void* const* d_in, const int* in_sizes, int n_in,
                              void* d_out, int out_size)
{
    const float* rgb   = (const float*)d_in[0];
    const float* ir    = (const float*)d_in[1];
    const float* wqkv  = (const float*)d_in[2];
    const float* wdw   = (const float*)d_in[3];
    const float* wproj = (const float*)d_in[4];
    const float* temp  = (const float*)d_in[5];
    float* out = (float*)d_out;

    k0_zero<<<288, 256>>>();

    dim3 g1(HW / 128, 3, 16);     // m0: 0,192,384
    k1_qkv<<<g1, 256>>>(rgb, ir, wqkv);

    dim3 g2(HW / 2048, C3, 16);
    k2_dw<<<g2, 256>>>(wdw);

    dim3 g3(8, NB * HEADS, 2);    // K-slices of 2048
    k3_gram<<<g3, 256>>>();

    k4_softmax_M<<<16, 192>>>(wproj, temp);

    dim3 g5(HW / 128, 1, 16);     // single m pass (192 rows)
    k5_out<<<g5, 256>>>(out);
}